// round 5
// baseline (speedup 1.0000x reference)
#include <cuda_runtime.h>
#include <cuda_bf16.h>
#include <cstdint>
#include <cstddef>

// Problem constants (fixed-shape problem)
#define BATCH 2
#define SEQ   2048
#define DIM   2048
#define HEADS 16
#define DH    128
#define NEGV  (-10000.0f)

// Scratch: qp (projected Q) and ctx (attention output, head-merged layout).
// __device__ globals are the sanctioned scratch mechanism (no allocations allowed).
__device__ float g_qp [(size_t)BATCH * SEQ * DIM];
__device__ float g_ctx[(size_t)BATCH * SEQ * DIM];

// Mask dtype flag: 1 if mask buffer is uint8 (1 byte/elem), 0 if int32 (4 bytes/elem).
__device__ int g_mask_u8;

// ---------------------------------------------------------------------------
// Detect mask storage width. jnp.bool_ may arrive as uint8 or be widened to
// int32 by the harness. If uint8: 4 random 0/1 bytes per word -> some word > 1
// with overwhelming probability over 16384 words. If int32: every word is 0/1.
// Deterministic for fixed inputs.
// ---------------------------------------------------------------------------
__global__ void detect_mask_kernel(const unsigned int* __restrict__ m)
{
    __shared__ int flag;
    if (threadIdx.x == 0) flag = 0;
    __syncthreads();
    int local = 0;
    for (int i = threadIdx.x; i < 16384; i += blockDim.x)
        if (m[i] > 1u) local = 1;
    if (local) atomicOr(&flag, 1);
    __syncthreads();
    if (threadIdx.x == 0) g_mask_u8 = flag;
}

// ---------------------------------------------------------------------------
// SGEMM: C[M,N] = A[M,K] @ W[N,K]^T   (both row-major, K contiguous — "NT")
// 128x128x32 tile, 256 threads, 8x8 per-thread register tile.
// ---------------------------------------------------------------------------
__global__ void __launch_bounds__(256, 2)
sgemm_nt(const float* __restrict__ A, const float* __restrict__ W,
         float* __restrict__ C, int M, int N, int K)
{
    constexpr int BM = 128, BN = 128, BK = 32;
    __shared__ float As[BK][BM + 4];   // As[k][m], pad keeps rows 16B-aligned (528B)
    __shared__ float Ws[BK][BN + 4];   // Ws[k][n]

    const int tid = threadIdx.x;
    const int bm  = blockIdx.y * BM;
    const int bn  = blockIdx.x * BN;
    const int tx  = tid & 15;
    const int ty  = tid >> 4;

    const float* Ap = A + (size_t)bm * K;
    const float* Wp = W + (size_t)bn * K;

    float acc[8][8];
    #pragma unroll
    for (int i = 0; i < 8; i++)
        #pragma unroll
        for (int j = 0; j < 8; j++) acc[i][j] = 0.f;

    for (int k0 = 0; k0 < K; k0 += BK) {
        // Load 128x32 tiles of A and W (1024 float4 each -> 4 per thread), coalesced.
        #pragma unroll
        for (int it = 0; it < 4; it++) {
            int li = tid + it * 256;
            int r  = li >> 3;      // 0..127
            int c4 = li & 7;       // 0..7 (float4 group within 32 k's)
            float4 av = *(const float4*)(Ap + (size_t)r * K + k0 + c4 * 4);
            As[c4*4+0][r] = av.x; As[c4*4+1][r] = av.y;
            As[c4*4+2][r] = av.z; As[c4*4+3][r] = av.w;
            float4 wv = *(const float4*)(Wp + (size_t)r * K + k0 + c4 * 4);
            Ws[c4*4+0][r] = wv.x; Ws[c4*4+1][r] = wv.y;
            Ws[c4*4+2][r] = wv.z; Ws[c4*4+3][r] = wv.w;
        }
        __syncthreads();

        #pragma unroll
        for (int kk = 0; kk < BK; kk++) {
            float4 a0 = *(const float4*)&As[kk][ty * 8];
            float4 a1 = *(const float4*)&As[kk][ty * 8 + 4];
            float4 b0 = *(const float4*)&Ws[kk][tx * 8];
            float4 b1 = *(const float4*)&Ws[kk][tx * 8 + 4];
            float a[8] = {a0.x, a0.y, a0.z, a0.w, a1.x, a1.y, a1.z, a1.w};
            float bb[8] = {b0.x, b0.y, b0.z, b0.w, b1.x, b1.y, b1.z, b1.w};
            #pragma unroll
            for (int i = 0; i < 8; i++)
                #pragma unroll
                for (int j = 0; j < 8; j++)
                    acc[i][j] += a[i] * bb[j];
        }
        __syncthreads();
    }

    // Write 8x8 tile (two float4 per row)
    #pragma unroll
    for (int i = 0; i < 8; i++) {
        float* Cr = C + (size_t)(bm + ty * 8 + i) * N + bn + tx * 8;
        float4 o0 = make_float4(acc[i][0], acc[i][1], acc[i][2], acc[i][3]);
        float4 o1 = make_float4(acc[i][4], acc[i][5], acc[i][6], acc[i][7]);
        *(float4*)(Cr)     = o0;
        *(float4*)(Cr + 4) = o1;
    }
}

// ---------------------------------------------------------------------------
// Flash attention (fp32, online softmax).
// Grid: (SEQ/64, BATCH*HEADS). Block: 256 threads (16x16 logical).
// Each CTA handles a 64-query tile of one (b, h); loops over 64-key blocks.
// ---------------------------------------------------------------------------
struct FlashSmem {
    float Qs[DH][65];     // Qs[d][q], pre-scaled by 1/sqrt(Dh)
    float Ks[DH][65];     // Ks[d][j]
    float Vs[64][DH];     // Vs[j][d]
    float Sb[64][65];     // score / probability tile
    float mrow[64];
    float lrow[64];
    float arow[64];
};

__global__ void __launch_bounds__(256, 1)
flash_kernel(const float* __restrict__ qp, const float* __restrict__ kp,
             const float* __restrict__ vp, const void* __restrict__ mask_raw,
             float* __restrict__ ctx)
{
    extern __shared__ char smem_raw[];
    FlashSmem* sm = reinterpret_cast<FlashSmem*>(smem_raw);

    const int tid = threadIdx.x;
    const int q0  = blockIdx.x * 64;
    const int bh  = blockIdx.y;
    const int b   = bh >> 4;
    const int h   = bh & 15;
    const int tx  = tid & 15;
    const int ty  = tid >> 4;
    const float scale = 0.08838834764831843f;  // 1/sqrt(128)
    const int mask_is_u8 = g_mask_u8;

    // ---- load Q tile (transposed to d-major, pre-scaled) ----
    const float* qbase = qp + ((size_t)b * SEQ + q0) * DIM + h * DH;
    #pragma unroll
    for (int it = 0; it < 8; it++) {
        int li = tid + it * 256;      // 0..2047 over (64 q x 32 d-groups)
        int d4 = li & 31;
        int q  = li >> 5;
        float4 v = *(const float4*)(qbase + (size_t)q * DIM + d4 * 4);
        sm->Qs[d4*4+0][q] = v.x * scale;
        sm->Qs[d4*4+1][q] = v.y * scale;
        sm->Qs[d4*4+2][q] = v.z * scale;
        sm->Qs[d4*4+3][q] = v.w * scale;
    }
    if (tid < 64) { sm->mrow[tid] = -1e30f; sm->lrow[tid] = 0.f; }

    float O[4][8];
    #pragma unroll
    for (int i = 0; i < 4; i++)
        #pragma unroll
        for (int c = 0; c < 8; c++) O[i][c] = 0.f;

    const unsigned char* mbase8 =
        (const unsigned char*)mask_raw + (size_t)b * SEQ * SEQ + (size_t)q0 * SEQ;
    const int* mbase32 =
        (const int*)mask_raw + (size_t)b * SEQ * SEQ + (size_t)q0 * SEQ;

    for (int k0 = 0; k0 < SEQ; k0 += 64) {
        __syncthreads();  // previous GEMM2 readers of Ks/Vs/Sb done; Q visible on iter 0

        // ---- load K (transposed) and V (row-major) tiles ----
        const float* kbase = kp + ((size_t)b * SEQ + k0) * DIM + h * DH;
        const float* vbase = vp + ((size_t)b * SEQ + k0) * DIM + h * DH;
        #pragma unroll
        for (int it = 0; it < 8; it++) {
            int li = tid + it * 256;
            int d4 = li & 31;
            int j  = li >> 5;
            float4 kv = *(const float4*)(kbase + (size_t)j * DIM + d4 * 4);
            sm->Ks[d4*4+0][j] = kv.x; sm->Ks[d4*4+1][j] = kv.y;
            sm->Ks[d4*4+2][j] = kv.z; sm->Ks[d4*4+3][j] = kv.w;
            float4 vv = *(const float4*)(vbase + (size_t)j * DIM + d4 * 4);
            *(float4*)&sm->Vs[j][d4 * 4] = vv;
        }
        __syncthreads();

        // ---- GEMM1: S(64x64) = Q(64x128) . K(64x128)^T ----
        float acc[4][4];
        #pragma unroll
        for (int i = 0; i < 4; i++)
            #pragma unroll
            for (int j = 0; j < 4; j++) acc[i][j] = 0.f;

        #pragma unroll 4
        for (int d = 0; d < DH; d++) {
            float a[4], bb[4];
            #pragma unroll
            for (int i = 0; i < 4; i++) a[i]  = sm->Qs[d][ty * 4 + i];
            #pragma unroll
            for (int j = 0; j < 4; j++) bb[j] = sm->Ks[d][tx * 4 + j];
            #pragma unroll
            for (int i = 0; i < 4; i++)
                #pragma unroll
                for (int j = 0; j < 4; j++)
                    acc[i][j] += a[i] * bb[j];
        }

        // ---- apply additive mask, store S tile (dual dtype path) ----
        if (mask_is_u8) {
            #pragma unroll
            for (int i = 0; i < 4; i++) {
                const unsigned char* mr =
                    mbase8 + (size_t)(ty * 4 + i) * SEQ + k0 + tx * 4;
                uchar4 mv = *(const uchar4*)mr;
                sm->Sb[ty*4+i][tx*4+0] = acc[i][0] + (mv.x ? NEGV : 0.f);
                sm->Sb[ty*4+i][tx*4+1] = acc[i][1] + (mv.y ? NEGV : 0.f);
                sm->Sb[ty*4+i][tx*4+2] = acc[i][2] + (mv.z ? NEGV : 0.f);
                sm->Sb[ty*4+i][tx*4+3] = acc[i][3] + (mv.w ? NEGV : 0.f);
            }
        } else {
            #pragma unroll
            for (int i = 0; i < 4; i++) {
                const int* mr = mbase32 + (size_t)(ty * 4 + i) * SEQ + k0 + tx * 4;
                int4 mv = *(const int4*)mr;
                sm->Sb[ty*4+i][tx*4+0] = acc[i][0] + (mv.x ? NEGV : 0.f);
                sm->Sb[ty*4+i][tx*4+1] = acc[i][1] + (mv.y ? NEGV : 0.f);
                sm->Sb[ty*4+i][tx*4+2] = acc[i][2] + (mv.z ? NEGV : 0.f);
                sm->Sb[ty*4+i][tx*4+3] = acc[i][3] + (mv.w ? NEGV : 0.f);
            }
        }
        __syncthreads();

        // ---- online softmax (one thread per query row) ----
        if (tid < 64) {
            int r = tid;
            float mold = sm->mrow[r];
            float mx = mold;
            #pragma unroll 8
            for (int j = 0; j < 64; j++) mx = fmaxf(mx, sm->Sb[r][j]);
            float al = __expf(mold - mx);
            float sum = 0.f;
            #pragma unroll 8
            for (int j = 0; j < 64; j++) {
                float p = __expf(sm->Sb[r][j] - mx);
                sm->Sb[r][j] = p;
                sum += p;
            }
            sm->mrow[r] = mx;
            sm->arow[r] = al;
            sm->lrow[r] = sm->lrow[r] * al + sum;
        }
        __syncthreads();

        // ---- rescale O and GEMM2: O += P(64x64) . V(64x128) ----
        #pragma unroll
        for (int i = 0; i < 4; i++) {
            float al = sm->arow[ty * 4 + i];
            #pragma unroll
            for (int c = 0; c < 8; c++) O[i][c] *= al;
        }
        #pragma unroll 2
        for (int kk = 0; kk < 64; kk++) {
            float4 v0 = *(const float4*)&sm->Vs[kk][tx * 8];
            float4 v1 = *(const float4*)&sm->Vs[kk][tx * 8 + 4];
            float vv[8] = {v0.x, v0.y, v0.z, v0.w, v1.x, v1.y, v1.z, v1.w};
            #pragma unroll
            for (int i = 0; i < 4; i++) {
                float p = sm->Sb[ty * 4 + i][kk];
                #pragma unroll
                for (int c = 0; c < 8; c++)
                    O[i][c] += p * vv[c];
            }
        }
    }

    // ---- finalize: divide by l and write ctx[b, q, h*DH + c] ----
    float* obase = ctx + ((size_t)b * SEQ + q0) * DIM + h * DH;
    #pragma unroll
    for (int i = 0; i < 4; i++) {
        float inv = 1.0f / sm->lrow[ty * 4 + i];
        float4 o0 = make_float4(O[i][0]*inv, O[i][1]*inv, O[i][2]*inv, O[i][3]*inv);
        float4 o1 = make_float4(O[i][4]*inv, O[i][5]*inv, O[i][6]*inv, O[i][7]*inv);
        float* orow = obase + (size_t)(ty * 4 + i) * DIM + tx * 8;
        *(float4*)(orow)     = o0;
        *(float4*)(orow + 4) = o1;
    }
}

// ---------------------------------------------------------------------------
// Launch
// ---------------------------------------------------------------------------
extern "C" void kernel_launch(void* const* d_in, const int* in_sizes, int n_in,
                              void* d_out, int out_size)
{
    const float* q    = (const float*)d_in[0];
    const float* k    = (const float*)d_in[1];
    const float* v    = (const float*)d_in[2];
    const void*  mask = d_in[3];                 // bool: uint8 OR int32 — detected on device
    const float* Wq   = (const float*)d_in[4];
    const float* Wk   = (const float*)d_in[5];
    const float* Wv   = (const float*)d_in[6];
    const float* Wo   = (const float*)d_in[7];

    float* out = (float*)d_out;
    const size_t plane = (size_t)BATCH * SEQ * DIM;
    float* kp = out + plane;       // output slot 2
    float* vp = out + 2 * plane;   // output slot 3

    float* qp  = nullptr;
    float* ctx = nullptr;
    cudaGetSymbolAddress((void**)&qp,  g_qp);
    cudaGetSymbolAddress((void**)&ctx, g_ctx);

    const int M = BATCH * SEQ;     // 4096
    dim3 gg(DIM / 128, M / 128);   // (16, 32)

    // Mask dtype detection (tiny, runs once per graph replay; deterministic)
    detect_mask_kernel<<<1, 256>>>((const unsigned int*)mask);

    // Projections
    sgemm_nt<<<gg, 256>>>(q, Wq, qp, M, DIM, DIM);
    sgemm_nt<<<gg, 256>>>(k, Wk, kp, M, DIM, DIM);
    sgemm_nt<<<gg, 256>>>(v, Wv, vp, M, DIM, DIM);

    // Attention
    cudaFuncSetAttribute(flash_kernel,
                         cudaFuncAttributeMaxDynamicSharedMemorySize,
                         (int)sizeof(FlashSmem));
    flash_kernel<<<dim3(SEQ / 64, BATCH * HEADS), 256, sizeof(FlashSmem)>>>(
        qp, kp, vp, mask, ctx);

    // Output projection
    sgemm_nt<<<gg, 256>>>(ctx, Wo, out, M, DIM, DIM);
}

// round 9
// speedup vs baseline: 1.5447x; 1.5447x over previous
#include <cuda_runtime.h>
#include <cuda_bf16.h>
#include <cstdint>
#include <cstddef>

// Problem constants (fixed-shape problem)
#define BATCH 2
#define SEQ   2048
#define DIM   2048
#define HEADS 16
#define DH    128
#define NEGV  (-10000.0f)

// Scratch (device globals = sanctioned scratch; no allocations allowed)
__device__ float g_qp [(size_t)BATCH * SEQ * DIM];
__device__ float g_ctx[(size_t)BATCH * SEQ * DIM];
__device__ int   g_mask_u8;

// ===========================================================================
// Helpers (baseline PTX only — NO tcgen05/TMEM: harness assembles for sm_103
// without the 'a' suffix, so only sm_80-era features are available)
// ===========================================================================
__device__ __forceinline__ uint32_t smem_u32(const void* p) {
    uint32_t a;
    asm("{ .reg .u64 t; cvta.to.shared.u64 t, %1; cvt.u32.u64 %0, t; }"
        : "=r"(a) : "l"(p));
    return a;
}

// ldmatrix x4: four 8x8 b16 matrices, addresses from all 32 lanes
__device__ __forceinline__ void ldmx4(uint32_t* r, uint32_t addr) {
    asm volatile("ldmatrix.sync.aligned.m8n8.x4.shared.b16 {%0,%1,%2,%3}, [%4];"
                 : "=r"(r[0]), "=r"(r[1]), "=r"(r[2]), "=r"(r[3]) : "r"(addr));
}

// mma m16n8k16 row.col f32 += bf16 * bf16
__device__ __forceinline__ void mma_bf16(float* c, const uint32_t* a,
                                         const uint32_t* b) {
    asm volatile(
        "mma.sync.aligned.m16n8k16.row.col.f32.bf16.bf16.f32 "
        "{%0,%1,%2,%3}, {%4,%5,%6,%7}, {%8,%9}, {%0,%1,%2,%3};"
        : "+f"(c[0]), "+f"(c[1]), "+f"(c[2]), "+f"(c[3])
        : "r"(a[0]), "r"(a[1]), "r"(a[2]), "r"(a[3]), "r"(b[0]), "r"(b[1]));
}

__device__ __forceinline__ void split_pack(float x0, float x1,
                                           uint32_t& hi, uint32_t& lo) {
    __nv_bfloat16 h0 = __float2bfloat16(x0);
    __nv_bfloat16 h1 = __float2bfloat16(x1);
    __nv_bfloat16 l0 = __float2bfloat16(x0 - __bfloat162float(h0));
    __nv_bfloat16 l1 = __float2bfloat16(x1 - __bfloat162float(h1));
    hi = (uint32_t)__bfloat16_as_ushort(h0) | ((uint32_t)__bfloat16_as_ushort(h1) << 16);
    lo = (uint32_t)__bfloat16_as_ushort(l0) | ((uint32_t)__bfloat16_as_ushort(l1) << 16);
}

// ===========================================================================
// Mask dtype detection (uint8 vs int32 storage of jnp.bool_)
// ===========================================================================
__global__ void detect_mask_kernel(const unsigned int* __restrict__ m)
{
    __shared__ int flag;
    if (threadIdx.x == 0) flag = 0;
    __syncthreads();
    int local = 0;
    for (int i = threadIdx.x; i < 16384; i += blockDim.x)
        if (m[i] > 1u) local = 1;
    if (local) atomicOr(&flag, 1);
    __syncthreads();
    if (threadIdx.x == 0) g_mask_u8 = flag;
}

// ===========================================================================
// Split-bf16 mma.sync GEMM: C[M,N] = A[M,K] @ W[N,K]^T   (fp32 I/O)
// Tile 128x128, BK=32; 8 warps in 2x4 grid, warp tile 64x32.
// 3 MMA passes per fragment pair: Ahi*Whi + Ahi*Wlo + Alo*Whi.
// Padded smem rows (40 bf16 = 80B stride) -> conflict-free ldmatrix.
// ===========================================================================
#define PK 40   // padded row length in bf16 elements (32 data + 8 pad)

__global__ void __launch_bounds__(256, 2)
gemm_mma(const float* __restrict__ A, const float* __restrict__ W,
         float* __restrict__ C, int M, int N, int K)
{
    __shared__ __nv_bfloat16 sAhi[128 * PK];
    __shared__ __nv_bfloat16 sAlo[128 * PK];
    __shared__ __nv_bfloat16 sWhi[128 * PK];
    __shared__ __nv_bfloat16 sWlo[128 * PK];

    const int tid  = threadIdx.x;
    const int lane = tid & 31;
    const int wid  = tid >> 5;
    const int wm   = wid >> 2;          // 0..1 -> m offset wm*64
    const int wn   = wid & 3;           // 0..3 -> n offset wn*32
    const int bm   = blockIdx.y * 128;
    const int bn   = blockIdx.x * 128;

    float acc[16][4];
    #pragma unroll
    for (int i = 0; i < 16; i++)
        #pragma unroll
        for (int j = 0; j < 4; j++) acc[i][j] = 0.f;

    const uint32_t bAhi = smem_u32(sAhi);
    const uint32_t bAlo = smem_u32(sAlo);
    const uint32_t bWhi = smem_u32(sWhi);
    const uint32_t bWlo = smem_u32(sWlo);

    // ldmatrix per-lane address offsets (bytes), constant across chunks
    // A (m16k16, x4): lanes 0-15 rows 0-15 col 0; lanes 16-31 rows 0-15 col 8
    const uint32_t offA =
        (uint32_t)(((wm * 64 + (lane & 15)) * PK + ((lane >> 4) << 3)) * 2);
    // B (two n8k16 tiles, x4): q=lane>>3: q0 rows n0-7 k0, q1 n0-7 k8,
    //                          q2 n8-15 k0, q3 n8-15 k8
    const uint32_t offB =
        (uint32_t)(((wn * 32 + (((lane >> 3) >> 1) << 3) + (lane & 7)) * PK
                    + (((lane >> 3) & 1) << 3)) * 2);

    // loader mapping: 1024 float4 per matrix per chunk; 4 per thread
    const int lr  = tid >> 3;            // base row (stride 32 over iters)
    const int lc4 = tid & 7;             // float4 group within 32 k's

    const int nchunks = K >> 5;          // K/32
    for (int ck = 0; ck < nchunks; ck++) {
        const int k0 = ck << 5;
        if (ck) __syncthreads();         // all warps done reading smem

        #pragma unroll
        for (int it = 0; it < 4; it++) {
            int r = lr + it * 32;
            uint32_t so = (uint32_t)((r * PK + lc4 * 4) * 2);   // byte offset
            uint32_t h01, l01, h23, l23;

            float4 av = *(const float4*)(A + (size_t)(bm + r) * K + k0 + lc4 * 4);
            split_pack(av.x, av.y, h01, l01);
            split_pack(av.z, av.w, h23, l23);
            *(uint32_t*)((char*)sAhi + so)     = h01;
            *(uint32_t*)((char*)sAhi + so + 4) = h23;
            *(uint32_t*)((char*)sAlo + so)     = l01;
            *(uint32_t*)((char*)sAlo + so + 4) = l23;

            float4 wv = *(const float4*)(W + (size_t)(bn + r) * K + k0 + lc4 * 4);
            split_pack(wv.x, wv.y, h01, l01);
            split_pack(wv.z, wv.w, h23, l23);
            *(uint32_t*)((char*)sWhi + so)     = h01;
            *(uint32_t*)((char*)sWhi + so + 4) = h23;
            *(uint32_t*)((char*)sWlo + so)     = l01;
            *(uint32_t*)((char*)sWlo + so + 4) = l23;
        }
        __syncthreads();

        #pragma unroll
        for (int ks = 0; ks < 2; ks++) {
            const uint32_t kb = (uint32_t)(ks * 16 * 2);   // 16 bf16 = 32B
            // B fragments: 2 pair-tiles x (hi, lo)
            uint32_t bh[8], bl[8];
            #pragma unroll
            for (int ntp = 0; ntp < 2; ntp++) {
                uint32_t ro = (uint32_t)(ntp * 16 * PK * 2);
                ldmx4(&bh[ntp * 4], bWhi + offB + ro + kb);
                ldmx4(&bl[ntp * 4], bWlo + offB + ro + kb);
            }
            #pragma unroll
            for (int mt = 0; mt < 4; mt++) {
                uint32_t ah[4], al[4];
                uint32_t ro = (uint32_t)(mt * 16 * PK * 2);
                ldmx4(ah, bAhi + offA + ro + kb);
                ldmx4(al, bAlo + offA + ro + kb);
                #pragma unroll
                for (int nt = 0; nt < 4; nt++) {
                    float* c = acc[mt * 4 + nt];
                    mma_bf16(c, ah, &bh[nt * 2]);
                    mma_bf16(c, ah, &bl[nt * 2]);
                    mma_bf16(c, al, &bh[nt * 2]);
                }
            }
        }
    }

    // Epilogue: fragment (g = lane/4, t = lane%4):
    // c0,c1 -> (row g,   col 2t..2t+1), c2,c3 -> (row g+8, col 2t..2t+1)
    const int g = lane >> 2;
    const int t = lane & 3;
    #pragma unroll
    for (int mt = 0; mt < 4; mt++) {
        #pragma unroll
        for (int nt = 0; nt < 4; nt++) {
            const float* c = acc[mt * 4 + nt];
            int row = bm + wm * 64 + mt * 16 + g;
            int col = bn + wn * 32 + nt * 8 + 2 * t;
            *(float2*)(C + (size_t)row * N + col)       = make_float2(c[0], c[1]);
            *(float2*)(C + (size_t)(row + 8) * N + col) = make_float2(c[2], c[3]);
        }
    }
}

// ===========================================================================
// Flash attention (fp32, online softmax) — unchanged from passing baseline
// ===========================================================================
struct FlashSmem {
    float Qs[DH][65];
    float Ks[DH][65];
    float Vs[64][DH];
    float Sb[64][65];
    float mrow[64];
    float lrow[64];
    float arow[64];
};

__global__ void __launch_bounds__(256, 1)
flash_kernel(const float* __restrict__ qp, const float* __restrict__ kp,
             const float* __restrict__ vp, const void* __restrict__ mask_raw,
             float* __restrict__ ctx)
{
    extern __shared__ char smem_raw[];
    FlashSmem* sm = reinterpret_cast<FlashSmem*>(smem_raw);

    const int tid = threadIdx.x;
    const int q0  = blockIdx.x * 64;
    const int bh  = blockIdx.y;
    const int b   = bh >> 4;
    const int h   = bh & 15;
    const int tx  = tid & 15;
    const int ty  = tid >> 4;
    const float scale = 0.08838834764831843f;  // 1/sqrt(128)
    const int mask_is_u8 = g_mask_u8;

    const float* qbase = qp + ((size_t)b * SEQ + q0) * DIM + h * DH;
    #pragma unroll
    for (int it = 0; it < 8; it++) {
        int li = tid + it * 256;
        int d4 = li & 31;
        int q  = li >> 5;
        float4 v = *(const float4*)(qbase + (size_t)q * DIM + d4 * 4);
        sm->Qs[d4*4+0][q] = v.x * scale;
        sm->Qs[d4*4+1][q] = v.y * scale;
        sm->Qs[d4*4+2][q] = v.z * scale;
        sm->Qs[d4*4+3][q] = v.w * scale;
    }
    if (tid < 64) { sm->mrow[tid] = -1e30f; sm->lrow[tid] = 0.f; }

    float O[4][8];
    #pragma unroll
    for (int i = 0; i < 4; i++)
        #pragma unroll
        for (int c = 0; c < 8; c++) O[i][c] = 0.f;

    const unsigned char* mbase8 =
        (const unsigned char*)mask_raw + (size_t)b * SEQ * SEQ + (size_t)q0 * SEQ;
    const int* mbase32 =
        (const int*)mask_raw + (size_t)b * SEQ * SEQ + (size_t)q0 * SEQ;

    for (int k0 = 0; k0 < SEQ; k0 += 64) {
        __syncthreads();

        const float* kbase = kp + ((size_t)b * SEQ + k0) * DIM + h * DH;
        const float* vbase = vp + ((size_t)b * SEQ + k0) * DIM + h * DH;
        #pragma unroll
        for (int it = 0; it < 8; it++) {
            int li = tid + it * 256;
            int d4 = li & 31;
            int j  = li >> 5;
            float4 kv = *(const float4*)(kbase + (size_t)j * DIM + d4 * 4);
            sm->Ks[d4*4+0][j] = kv.x; sm->Ks[d4*4+1][j] = kv.y;
            sm->Ks[d4*4+2][j] = kv.z; sm->Ks[d4*4+3][j] = kv.w;
            float4 vv = *(const float4*)(vbase + (size_t)j * DIM + d4 * 4);
            *(float4*)&sm->Vs[j][d4 * 4] = vv;
        }
        __syncthreads();

        float accs[4][4];
        #pragma unroll
        for (int i = 0; i < 4; i++)
            #pragma unroll
            for (int j = 0; j < 4; j++) accs[i][j] = 0.f;

        #pragma unroll 4
        for (int d = 0; d < DH; d++) {
            float a[4], bb[4];
            #pragma unroll
            for (int i = 0; i < 4; i++) a[i]  = sm->Qs[d][ty * 4 + i];
            #pragma unroll
            for (int j = 0; j < 4; j++) bb[j] = sm->Ks[d][tx * 4 + j];
            #pragma unroll
            for (int i = 0; i < 4; i++)
                #pragma unroll
                for (int j = 0; j < 4; j++)
                    accs[i][j] += a[i] * bb[j];
        }

        if (mask_is_u8) {
            #pragma unroll
            for (int i = 0; i < 4; i++) {
                const unsigned char* mr =
                    mbase8 + (size_t)(ty * 4 + i) * SEQ + k0 + tx * 4;
                uchar4 mv = *(const uchar4*)mr;
                sm->Sb[ty*4+i][tx*4+0] = accs[i][0] + (mv.x ? NEGV : 0.f);
                sm->Sb[ty*4+i][tx*4+1] = accs[i][1] + (mv.y ? NEGV : 0.f);
                sm->Sb[ty*4+i][tx*4+2] = accs[i][2] + (mv.z ? NEGV : 0.f);
                sm->Sb[ty*4+i][tx*4+3] = accs[i][3] + (mv.w ? NEGV : 0.f);
            }
        } else {
            #pragma unroll
            for (int i = 0; i < 4; i++) {
                const int* mr = mbase32 + (size_t)(ty * 4 + i) * SEQ + k0 + tx * 4;
                int4 mv = *(const int4*)mr;
                sm->Sb[ty*4+i][tx*4+0] = accs[i][0] + (mv.x ? NEGV : 0.f);
                sm->Sb[ty*4+i][tx*4+1] = accs[i][1] + (mv.y ? NEGV : 0.f);
                sm->Sb[ty*4+i][tx*4+2] = accs[i][2] + (mv.z ? NEGV : 0.f);
                sm->Sb[ty*4+i][tx*4+3] = accs[i][3] + (mv.w ? NEGV : 0.f);
            }
        }
        __syncthreads();

        if (tid < 64) {
            int r = tid;
            float mold = sm->mrow[r];
            float mx = mold;
            #pragma unroll 8
            for (int j = 0; j < 64; j++) mx = fmaxf(mx, sm->Sb[r][j]);
            float al = __expf(mold - mx);
            float sum = 0.f;
            #pragma unroll 8
            for (int j = 0; j < 64; j++) {
                float p = __expf(sm->Sb[r][j] - mx);
                sm->Sb[r][j] = p;
                sum += p;
            }
            sm->mrow[r] = mx;
            sm->arow[r] = al;
            sm->lrow[r] = sm->lrow[r] * al + sum;
        }
        __syncthreads();

        #pragma unroll
        for (int i = 0; i < 4; i++) {
            float al = sm->arow[ty * 4 + i];
            #pragma unroll
            for (int c = 0; c < 8; c++) O[i][c] *= al;
        }
        #pragma unroll 2
        for (int kk = 0; kk < 64; kk++) {
            float4 v0 = *(const float4*)&sm->Vs[kk][tx * 8];
            float4 v1 = *(const float4*)&sm->Vs[kk][tx * 8 + 4];
            float vv[8] = {v0.x, v0.y, v0.z, v0.w, v1.x, v1.y, v1.z, v1.w};
            #pragma unroll
            for (int i = 0; i < 4; i++) {
                float p = sm->Sb[ty * 4 + i][kk];
                #pragma unroll
                for (int c = 0; c < 8; c++)
                    O[i][c] += p * vv[c];
            }
        }
    }

    float* obase = ctx + ((size_t)b * SEQ + q0) * DIM + h * DH;
    #pragma unroll
    for (int i = 0; i < 4; i++) {
        float inv = 1.0f / sm->lrow[ty * 4 + i];
        float4 o0 = make_float4(O[i][0]*inv, O[i][1]*inv, O[i][2]*inv, O[i][3]*inv);
        float4 o1 = make_float4(O[i][4]*inv, O[i][5]*inv, O[i][6]*inv, O[i][7]*inv);
        float* orow = obase + (size_t)(ty * 4 + i) * DIM + tx * 8;
        *(float4*)(orow)     = o0;
        *(float4*)(orow + 4) = o1;
    }
}

// ===========================================================================
// Launch
// ===========================================================================
extern "C" void kernel_launch(void* const* d_in, const int* in_sizes, int n_in,
                              void* d_out, int out_size)
{
    const float* q    = (const float*)d_in[0];
    const float* k    = (const float*)d_in[1];
    const float* v    = (const float*)d_in[2];
    const void*  mask = d_in[3];
    const float* Wq   = (const float*)d_in[4];
    const float* Wk   = (const float*)d_in[5];
    const float* Wv   = (const float*)d_in[6];
    const float* Wo   = (const float*)d_in[7];

    float* out = (float*)d_out;
    const size_t plane = (size_t)BATCH * SEQ * DIM;
    float* kp = out + plane;
    float* vp = out + 2 * plane;

    float* qp  = nullptr;
    float* ctx = nullptr;
    cudaGetSymbolAddress((void**)&qp,  g_qp);
    cudaGetSymbolAddress((void**)&ctx, g_ctx);

    const int M = BATCH * SEQ;           // 4096
    dim3 gg(DIM / 128, M / 128);         // (16, 32)

    detect_mask_kernel<<<1, 256>>>((const unsigned int*)mask);

    // Projections (split-bf16 mma.sync tensor-core GEMM)
    gemm_mma<<<gg, 256>>>(q, Wq, qp, M, DIM, DIM);
    gemm_mma<<<gg, 256>>>(k, Wk, kp, M, DIM, DIM);
    gemm_mma<<<gg, 256>>>(v, Wv, vp, M, DIM, DIM);

    // Attention
    cudaFuncSetAttribute(flash_kernel,
                         cudaFuncAttributeMaxDynamicSharedMemorySize,
                         (int)sizeof(FlashSmem));
    flash_kernel<<<dim3(SEQ / 64, BATCH * HEADS), 256, sizeof(FlashSmem)>>>(
        qp, kp, vp, mask, ctx);

    // Output projection
    gemm_mma<<<gg, 256>>>(ctx, Wo, out, M, DIM, DIM);
}

// round 11
// speedup vs baseline: 2.8256x; 1.8292x over previous
#include <cuda_runtime.h>
#include <cuda_bf16.h>
#include <cstdint>
#include <cstddef>

// Problem constants (fixed-shape problem)
#define BATCH 2
#define SEQ   2048
#define DIM   2048
#define HEADS 16
#define DH    128
#define NEGV  (-10000.0f)

// Scratch (device globals = sanctioned scratch; no allocations allowed)
__device__ float g_qp [(size_t)BATCH * SEQ * DIM];
__device__ float g_ctx[(size_t)BATCH * SEQ * DIM];
__device__ int   g_mask_u8;

// ===========================================================================
// Helpers (baseline PTX only — NO tcgen05/TMEM: harness assembles for sm_103
// without the 'a' suffix, so only sm_80-era features are available)
// ===========================================================================
__device__ __forceinline__ uint32_t smem_u32(const void* p) {
    uint32_t a;
    asm("{ .reg .u64 t; cvta.to.shared.u64 t, %1; cvt.u32.u64 %0, t; }"
        : "=r"(a) : "l"(p));
    return a;
}

// ldmatrix x4: four 8x8 b16 matrices
__device__ __forceinline__ void ldmx4(uint32_t* r, uint32_t addr) {
    asm volatile("ldmatrix.sync.aligned.m8n8.x4.shared.b16 {%0,%1,%2,%3}, [%4];"
                 : "=r"(r[0]), "=r"(r[1]), "=r"(r[2]), "=r"(r[3]) : "r"(addr));
}

// ldmatrix x4 transposed (for V as B-operand from row-major [key][dh])
__device__ __forceinline__ void ldmx4t(uint32_t* r, uint32_t addr) {
    asm volatile("ldmatrix.sync.aligned.m8n8.x4.trans.shared.b16 {%0,%1,%2,%3}, [%4];"
                 : "=r"(r[0]), "=r"(r[1]), "=r"(r[2]), "=r"(r[3]) : "r"(addr));
}

// mma m16n8k16 row.col f32 += bf16 * bf16
__device__ __forceinline__ void mma_bf16(float* c, const uint32_t* a,
                                         const uint32_t* b) {
    asm volatile(
        "mma.sync.aligned.m16n8k16.row.col.f32.bf16.bf16.f32 "
        "{%0,%1,%2,%3}, {%4,%5,%6,%7}, {%8,%9}, {%0,%1,%2,%3};"
        : "+f"(c[0]), "+f"(c[1]), "+f"(c[2]), "+f"(c[3])
        : "r"(a[0]), "r"(a[1]), "r"(a[2]), "r"(a[3]), "r"(b[0]), "r"(b[1]));
}

__device__ __forceinline__ void split_pack(float x0, float x1,
                                           uint32_t& hi, uint32_t& lo) {
    __nv_bfloat16 h0 = __float2bfloat16(x0);
    __nv_bfloat16 h1 = __float2bfloat16(x1);
    __nv_bfloat16 l0 = __float2bfloat16(x0 - __bfloat162float(h0));
    __nv_bfloat16 l1 = __float2bfloat16(x1 - __bfloat162float(h1));
    hi = (uint32_t)__bfloat16_as_ushort(h0) | ((uint32_t)__bfloat16_as_ushort(h1) << 16);
    lo = (uint32_t)__bfloat16_as_ushort(l0) | ((uint32_t)__bfloat16_as_ushort(l1) << 16);
}

// ===========================================================================
// Mask dtype detection (uint8 vs int32 storage of jnp.bool_)
// ===========================================================================
__global__ void detect_mask_kernel(const unsigned int* __restrict__ m)
{
    __shared__ int flag;
    if (threadIdx.x == 0) flag = 0;
    __syncthreads();
    int local = 0;
    for (int i = threadIdx.x; i < 16384; i += blockDim.x)
        if (m[i] > 1u) local = 1;
    if (local) atomicOr(&flag, 1);
    __syncthreads();
    if (threadIdx.x == 0) g_mask_u8 = flag;
}

// ===========================================================================
// Split-bf16 mma.sync GEMM: C[M,N] = A[M,K] @ W[N,K]^T  (fp32 I/O) — R9 proven
// ===========================================================================
#define PK 40   // padded row length in bf16 elements (32 data + 8 pad)

__global__ void __launch_bounds__(256, 2)
gemm_mma(const float* __restrict__ A, const float* __restrict__ W,
         float* __restrict__ C, int M, int N, int K)
{
    __shared__ __nv_bfloat16 sAhi[128 * PK];
    __shared__ __nv_bfloat16 sAlo[128 * PK];
    __shared__ __nv_bfloat16 sWhi[128 * PK];
    __shared__ __nv_bfloat16 sWlo[128 * PK];

    const int tid  = threadIdx.x;
    const int lane = tid & 31;
    const int wid  = tid >> 5;
    const int wm   = wid >> 2;
    const int wn   = wid & 3;
    const int bm   = blockIdx.y * 128;
    const int bn   = blockIdx.x * 128;

    float acc[16][4];
    #pragma unroll
    for (int i = 0; i < 16; i++)
        #pragma unroll
        for (int j = 0; j < 4; j++) acc[i][j] = 0.f;

    const uint32_t bAhi = smem_u32(sAhi);
    const uint32_t bAlo = smem_u32(sAlo);
    const uint32_t bWhi = smem_u32(sWhi);
    const uint32_t bWlo = smem_u32(sWlo);

    const uint32_t offA =
        (uint32_t)(((wm * 64 + (lane & 15)) * PK + ((lane >> 4) << 3)) * 2);
    const uint32_t offB =
        (uint32_t)(((wn * 32 + (((lane >> 3) >> 1) << 3) + (lane & 7)) * PK
                    + (((lane >> 3) & 1) << 3)) * 2);

    const int lr  = tid >> 3;
    const int lc4 = tid & 7;

    const int nchunks = K >> 5;
    for (int ck = 0; ck < nchunks; ck++) {
        const int k0 = ck << 5;
        if (ck) __syncthreads();

        #pragma unroll
        for (int it = 0; it < 4; it++) {
            int r = lr + it * 32;
            uint32_t so = (uint32_t)((r * PK + lc4 * 4) * 2);
            uint32_t h01, l01, h23, l23;

            float4 av = *(const float4*)(A + (size_t)(bm + r) * K + k0 + lc4 * 4);
            split_pack(av.x, av.y, h01, l01);
            split_pack(av.z, av.w, h23, l23);
            *(uint32_t*)((char*)sAhi + so)     = h01;
            *(uint32_t*)((char*)sAhi + so + 4) = h23;
            *(uint32_t*)((char*)sAlo + so)     = l01;
            *(uint32_t*)((char*)sAlo + so + 4) = l23;

            float4 wv = *(const float4*)(W + (size_t)(bn + r) * K + k0 + lc4 * 4);
            split_pack(wv.x, wv.y, h01, l01);
            split_pack(wv.z, wv.w, h23, l23);
            *(uint32_t*)((char*)sWhi + so)     = h01;
            *(uint32_t*)((char*)sWhi + so + 4) = h23;
            *(uint32_t*)((char*)sWlo + so)     = l01;
            *(uint32_t*)((char*)sWlo + so + 4) = l23;
        }
        __syncthreads();

        #pragma unroll
        for (int ks = 0; ks < 2; ks++) {
            const uint32_t kb = (uint32_t)(ks * 16 * 2);
            uint32_t bh[8], bl[8];
            #pragma unroll
            for (int ntp = 0; ntp < 2; ntp++) {
                uint32_t ro = (uint32_t)(ntp * 16 * PK * 2);
                ldmx4(&bh[ntp * 4], bWhi + offB + ro + kb);
                ldmx4(&bl[ntp * 4], bWlo + offB + ro + kb);
            }
            #pragma unroll
            for (int mt = 0; mt < 4; mt++) {
                uint32_t ah[4], al[4];
                uint32_t ro = (uint32_t)(mt * 16 * PK * 2);
                ldmx4(ah, bAhi + offA + ro + kb);
                ldmx4(al, bAlo + offA + ro + kb);
                #pragma unroll
                for (int nt = 0; nt < 4; nt++) {
                    float* c = acc[mt * 4 + nt];
                    mma_bf16(c, ah, &bh[nt * 2]);
                    mma_bf16(c, ah, &bl[nt * 2]);
                    mma_bf16(c, al, &bh[nt * 2]);
                }
            }
        }
    }

    const int g = lane >> 2;
    const int t = lane & 3;
    #pragma unroll
    for (int mt = 0; mt < 4; mt++) {
        #pragma unroll
        for (int nt = 0; nt < 4; nt++) {
            const float* c = acc[mt * 4 + nt];
            int row = bm + wm * 64 + mt * 16 + g;
            int col = bn + wn * 32 + nt * 8 + 2 * t;
            *(float2*)(C + (size_t)row * N + col)       = make_float2(c[0], c[1]);
            *(float2*)(C + (size_t)(row + 8) * N + col) = make_float2(c[2], c[3]);
        }
    }
}

// ===========================================================================
// Flash attention with split-bf16 mma.sync.
// BQ=128, BKV=64. 8 warps; warp w owns q rows [w*16, w*16+16) -> softmax
// reductions are intra-quad shuffles only.
// QK^T: split Q (scale folded) x split K, 3 combos.
// P.V:  P split in-register (acc->A-frag repack), V split in smem,
//       B-fragments via ldmatrix.x4.trans on row-major [key][dh].
// ===========================================================================
#define PKQ 136   // padded row length (128 dh bf16 + 8)
#define PMK 72    // mask tile padded row (64 + 8), multiple of 4

struct FlashSmem2 {
    __nv_bfloat16 Qhi[128 * PKQ];
    __nv_bfloat16 Qlo[128 * PKQ];
    __nv_bfloat16 Khi[64 * PKQ];
    __nv_bfloat16 Klo[64 * PKQ];
    __nv_bfloat16 Vhi[64 * PKQ];
    __nv_bfloat16 Vlo[64 * PKQ];
    unsigned char Msk[128 * PMK];
};   // 148480 bytes

__global__ void __launch_bounds__(256, 1)
flash_mma(const float* __restrict__ qp, const float* __restrict__ kp,
          const float* __restrict__ vp, const void* __restrict__ mask_raw,
          float* __restrict__ ctx)
{
    extern __shared__ char smraw[];
    FlashSmem2* sm = reinterpret_cast<FlashSmem2*>(smraw);

    const int tid  = threadIdx.x;
    const int lane = tid & 31;
    const int w    = tid >> 5;
    const int q0   = blockIdx.x * 128;
    const int bh   = blockIdx.y;
    const int b    = bh >> 4;
    const int h    = bh & 15;
    const float scale = 0.08838834764831843f;   // 1/sqrt(128)
    const int mu8 = g_mask_u8;

    // ---- load Q tile (128 x 128), split hi/lo with scale folded ----
    const float* qbase = qp + ((size_t)b * SEQ + q0) * DIM + h * DH;
    #pragma unroll
    for (int it = 0; it < 16; it++) {
        int li = tid + it * 256;
        int r  = li >> 5, c4 = li & 31;
        float4 qv = *(const float4*)(qbase + (size_t)r * DIM + c4 * 4);
        uint32_t h01, l01, h23, l23;
        split_pack(qv.x * scale, qv.y * scale, h01, l01);
        split_pack(qv.z * scale, qv.w * scale, h23, l23);
        uint32_t so = (uint32_t)((r * PKQ + c4 * 4) * 2);
        *(uint32_t*)((char*)sm->Qhi + so)     = h01;
        *(uint32_t*)((char*)sm->Qhi + so + 4) = h23;
        *(uint32_t*)((char*)sm->Qlo + so)     = l01;
        *(uint32_t*)((char*)sm->Qlo + so + 4) = l23;
    }

    const uint32_t bQhi = smem_u32(sm->Qhi), bQlo = smem_u32(sm->Qlo);
    const uint32_t bKhi = smem_u32(sm->Khi), bKlo = smem_u32(sm->Klo);
    const uint32_t bVhi = smem_u32(sm->Vhi), bVlo = smem_u32(sm->Vlo);

    // ldmatrix per-lane offsets (bytes)
    const uint32_t offA =
        (uint32_t)(((w * 16 + (lane & 15)) * PKQ + ((lane >> 4) << 3)) * 2);
    const uint32_t offB =
        (uint32_t)(((((lane >> 4) & 1) * 8 + (lane & 7)) * PKQ
                    + (((lane >> 3) & 1) << 3)) * 2);
    const uint32_t offV =
        (uint32_t)((((lane & 7) + (((lane >> 3) & 1) << 3)) * PKQ
                    + (((lane >> 4) & 1) << 3)) * 2);

    float Oa[16][4];
    #pragma unroll
    for (int i = 0; i < 16; i++)
        #pragma unroll
        for (int j = 0; j < 4; j++) Oa[i][j] = 0.f;

    float m_g = -1e30f, m_g8 = -1e30f, l_g = 0.f, l_g8 = 0.f;
    const int g = lane >> 2, t = lane & 3;
    const int rg = w * 16 + g, rg8 = rg + 8;

    for (int k0 = 0; k0 < SEQ; k0 += 64) {
        __syncthreads();   // smem reuse guard (also covers initial Q stores)

        // ---- load K, V tiles (64 x 128), split hi/lo ----
        const float* kb_ = kp + ((size_t)b * SEQ + k0) * DIM + h * DH;
        const float* vb_ = vp + ((size_t)b * SEQ + k0) * DIM + h * DH;
        #pragma unroll
        for (int it = 0; it < 8; it++) {
            int li = tid + it * 256;
            int r  = li >> 5, c4 = li & 31;
            uint32_t so = (uint32_t)((r * PKQ + c4 * 4) * 2);
            uint32_t h01, l01, h23, l23;

            float4 kv = *(const float4*)(kb_ + (size_t)r * DIM + c4 * 4);
            split_pack(kv.x, kv.y, h01, l01);
            split_pack(kv.z, kv.w, h23, l23);
            *(uint32_t*)((char*)sm->Khi + so)     = h01;
            *(uint32_t*)((char*)sm->Khi + so + 4) = h23;
            *(uint32_t*)((char*)sm->Klo + so)     = l01;
            *(uint32_t*)((char*)sm->Klo + so + 4) = l23;

            float4 vv = *(const float4*)(vb_ + (size_t)r * DIM + c4 * 4);
            split_pack(vv.x, vv.y, h01, l01);
            split_pack(vv.z, vv.w, h23, l23);
            *(uint32_t*)((char*)sm->Vhi + so)     = h01;
            *(uint32_t*)((char*)sm->Vhi + so + 4) = h23;
            *(uint32_t*)((char*)sm->Vlo + so)     = l01;
            *(uint32_t*)((char*)sm->Vlo + so + 4) = l23;
        }

        // ---- stage mask tile (128 q x 64 k) as u8 ----
        if (mu8) {
            const unsigned char* mb = (const unsigned char*)mask_raw
                + (size_t)b * SEQ * SEQ + (size_t)q0 * SEQ + k0;
            #pragma unroll
            for (int it = 0; it < 8; it++) {
                int li = tid + it * 256;
                int r  = li >> 4, c4 = li & 15;
                *(uint32_t*)(sm->Msk + r * PMK + c4 * 4) =
                    *(const uint32_t*)(mb + (size_t)r * SEQ + c4 * 4);
            }
        } else {
            const int* mb = (const int*)mask_raw
                + (size_t)b * SEQ * SEQ + (size_t)q0 * SEQ + k0;
            #pragma unroll
            for (int it = 0; it < 8; it++) {
                int li = tid + it * 256;
                int r  = li >> 4, c4 = li & 15;
                int4 mv = *(const int4*)(mb + (size_t)r * SEQ + c4 * 4);
                uint32_t pk = (mv.x ? 1u : 0u) | ((mv.y ? 1u : 0u) << 8)
                            | ((mv.z ? 1u : 0u) << 16) | ((mv.w ? 1u : 0u) << 24);
                *(uint32_t*)(sm->Msk + r * PMK + c4 * 4) = pk;
            }
        }
        __syncthreads();

        // ---- S = Q . K^T  (split bf16, 3 combos) ----
        float sacc[8][4];
        #pragma unroll
        for (int i = 0; i < 8; i++)
            #pragma unroll
            for (int j = 0; j < 4; j++) sacc[i][j] = 0.f;

        #pragma unroll
        for (int ks = 0; ks < 8; ks++) {
            const uint32_t kb = (uint32_t)(ks * 32);   // 16 bf16 = 32B
            uint32_t qh_[4], ql_[4];
            ldmx4(qh_, bQhi + offA + kb);
            ldmx4(ql_, bQlo + offA + kb);
            #pragma unroll
            for (int ntp = 0; ntp < 4; ntp++) {
                const uint32_t ro = (uint32_t)(ntp * 16 * PKQ * 2);
                uint32_t bh_[4], bl_[4];
                ldmx4(bh_, bKhi + offB + ro + kb);
                ldmx4(bl_, bKlo + offB + ro + kb);
                #pragma unroll
                for (int hf = 0; hf < 2; hf++) {
                    float* c = sacc[2 * ntp + hf];
                    mma_bf16(c, qh_, &bh_[hf * 2]);
                    mma_bf16(c, qh_, &bl_[hf * 2]);
                    mma_bf16(c, ql_, &bh_[hf * 2]);
                }
            }
        }

        // ---- mask + online softmax (intra-quad reductions) ----
        float mg = -1e30f, mg8 = -1e30f;
        #pragma unroll
        for (int nt = 0; nt < 8; nt++) {
            float* c = sacc[nt];
            int colb = nt * 8 + 2 * t;
            uchar2 ma  = *(const uchar2*)(sm->Msk + rg  * PMK + colb);
            uchar2 mb2 = *(const uchar2*)(sm->Msk + rg8 * PMK + colb);
            c[0] += ma.x  ? NEGV : 0.f;
            c[1] += ma.y  ? NEGV : 0.f;
            c[2] += mb2.x ? NEGV : 0.f;
            c[3] += mb2.y ? NEGV : 0.f;
            mg  = fmaxf(mg,  fmaxf(c[0], c[1]));
            mg8 = fmaxf(mg8, fmaxf(c[2], c[3]));
        }
        mg  = fmaxf(mg,  __shfl_xor_sync(0xffffffffu, mg, 1));
        mg  = fmaxf(mg,  __shfl_xor_sync(0xffffffffu, mg, 2));
        mg8 = fmaxf(mg8, __shfl_xor_sync(0xffffffffu, mg8, 1));
        mg8 = fmaxf(mg8, __shfl_xor_sync(0xffffffffu, mg8, 2));

        float mn  = fmaxf(m_g,  mg);
        float mn8 = fmaxf(m_g8, mg8);
        float ag  = __expf(m_g  - mn);
        float ag8 = __expf(m_g8 - mn8);
        m_g = mn; m_g8 = mn8;

        float sg = 0.f, sg8 = 0.f;
        #pragma unroll
        for (int nt = 0; nt < 8; nt++) {
            float* c = sacc[nt];
            c[0] = __expf(c[0] - mn);
            c[1] = __expf(c[1] - mn);
            c[2] = __expf(c[2] - mn8);
            c[3] = __expf(c[3] - mn8);
            sg  += c[0] + c[1];
            sg8 += c[2] + c[3];
        }
        sg  += __shfl_xor_sync(0xffffffffu, sg, 1);
        sg  += __shfl_xor_sync(0xffffffffu, sg, 2);
        sg8 += __shfl_xor_sync(0xffffffffu, sg8, 1);
        sg8 += __shfl_xor_sync(0xffffffffu, sg8, 2);
        l_g  = l_g  * ag  + sg;
        l_g8 = l_g8 * ag8 + sg8;

        #pragma unroll
        for (int nt = 0; nt < 16; nt++) {
            Oa[nt][0] *= ag;  Oa[nt][1] *= ag;
            Oa[nt][2] *= ag8; Oa[nt][3] *= ag8;
        }

        // ---- O += P . V  (P split in-register, V split in smem) ----
        #pragma unroll
        for (int ks = 0; ks < 4; ks++) {
            uint32_t ph_[4], pl_[4];
            split_pack(sacc[2*ks][0],   sacc[2*ks][1],   ph_[0], pl_[0]);
            split_pack(sacc[2*ks][2],   sacc[2*ks][3],   ph_[1], pl_[1]);
            split_pack(sacc[2*ks+1][0], sacc[2*ks+1][1], ph_[2], pl_[2]);
            split_pack(sacc[2*ks+1][2], sacc[2*ks+1][3], ph_[3], pl_[3]);
            const uint32_t kro = (uint32_t)(ks * 16 * PKQ * 2);
            #pragma unroll
            for (int ntp = 0; ntp < 8; ntp++) {
                const uint32_t no = (uint32_t)(ntp * 16 * 2);
                uint32_t vh_[4], vl_[4];
                ldmx4t(vh_, bVhi + offV + kro + no);
                ldmx4t(vl_, bVlo + offV + kro + no);
                #pragma unroll
                for (int hf = 0; hf < 2; hf++) {
                    float* o = Oa[2 * ntp + hf];
                    mma_bf16(o, ph_, &vh_[hf * 2]);
                    mma_bf16(o, ph_, &vl_[hf * 2]);
                    mma_bf16(o, pl_, &vh_[hf * 2]);
                }
            }
        }
    }

    // ---- finalize: O / l, write ctx[b, q, h*DH + col] ----
    const float ig  = 1.f / l_g;
    const float ig8 = 1.f / l_g8;
    float* ob = ctx + ((size_t)b * SEQ + q0) * DIM + h * DH;
    #pragma unroll
    for (int nt = 0; nt < 16; nt++) {
        int col = nt * 8 + 2 * t;
        *(float2*)(ob + (size_t)rg  * DIM + col) =
            make_float2(Oa[nt][0] * ig,  Oa[nt][1] * ig);
        *(float2*)(ob + (size_t)rg8 * DIM + col) =
            make_float2(Oa[nt][2] * ig8, Oa[nt][3] * ig8);
    }
}

// ===========================================================================
// Launch
// ===========================================================================
extern "C" void kernel_launch(void* const* d_in, const int* in_sizes, int n_in,
                              void* d_out, int out_size)
{
    const float* q    = (const float*)d_in[0];
    const float* k    = (const float*)d_in[1];
    const float* v    = (const float*)d_in[2];
    const void*  mask = d_in[3];
    const float* Wq   = (const float*)d_in[4];
    const float* Wk   = (const float*)d_in[5];
    const float* Wv   = (const float*)d_in[6];
    const float* Wo   = (const float*)d_in[7];

    float* out = (float*)d_out;
    const size_t plane = (size_t)BATCH * SEQ * DIM;
    float* kp = out + plane;
    float* vp = out + 2 * plane;

    float* qp  = nullptr;
    float* ctx = nullptr;
    cudaGetSymbolAddress((void**)&qp,  g_qp);
    cudaGetSymbolAddress((void**)&ctx, g_ctx);

    const int M = BATCH * SEQ;           // 4096
    dim3 gg(DIM / 128, M / 128);         // (16, 32)

    detect_mask_kernel<<<1, 256>>>((const unsigned int*)mask);

    // Projections (split-bf16 mma.sync tensor-core GEMM)
    gemm_mma<<<gg, 256>>>(q, Wq, qp, M, DIM, DIM);
    gemm_mma<<<gg, 256>>>(k, Wk, kp, M, DIM, DIM);
    gemm_mma<<<gg, 256>>>(v, Wv, vp, M, DIM, DIM);

    // Attention (split-bf16 mma.sync flash)
    cudaFuncSetAttribute(flash_mma,
                         cudaFuncAttributeMaxDynamicSharedMemorySize,
                         (int)sizeof(FlashSmem2));
    flash_mma<<<dim3(SEQ / 128, BATCH * HEADS), 256, sizeof(FlashSmem2)>>>(
        qp, kp, vp, mask, ctx);

    // Output projection
    gemm_mma<<<gg, 256>>>(ctx, Wo, out, M, DIM, DIM);
}

// round 12
// speedup vs baseline: 3.0155x; 1.0672x over previous
#include <cuda_runtime.h>
#include <cuda_bf16.h>
#include <cstdint>
#include <cstddef>

// Problem constants (fixed-shape problem)
#define BATCH 2
#define SEQ   2048
#define DIM   2048
#define HEADS 16
#define DH    128
#define NEGV  (-10000.0f)
#define MROWS (BATCH * SEQ)          // 4096

// Scratch (device globals = sanctioned scratch; no allocations allowed)
__device__ __nv_bfloat16 g_Ahi[(size_t)MROWS * DIM];
__device__ __nv_bfloat16 g_Alo[(size_t)MROWS * DIM];
__device__ __nv_bfloat16 g_Whi[(size_t)DIM * DIM];
__device__ __nv_bfloat16 g_Wlo[(size_t)DIM * DIM];
__device__ __nv_bfloat16 g_Qhi[(size_t)MROWS * DIM];
__device__ __nv_bfloat16 g_Qlo[(size_t)MROWS * DIM];
__device__ __nv_bfloat16 g_Khi[(size_t)MROWS * DIM];
__device__ __nv_bfloat16 g_Klo[(size_t)MROWS * DIM];
__device__ __nv_bfloat16 g_Vhi[(size_t)MROWS * DIM];
__device__ __nv_bfloat16 g_Vlo[(size_t)MROWS * DIM];
__device__ float         g_ctx[(size_t)MROWS * DIM];
__device__ int           g_mask_u8;

// ===========================================================================
// Helpers (baseline PTX only — NO tcgen05/TMEM: harness assembles for sm_103
// without the 'a' suffix; sm_80-era features only)
// ===========================================================================
__device__ __forceinline__ uint32_t smem_u32(const void* p) {
    uint32_t a;
    asm("{ .reg .u64 t; cvta.to.shared.u64 t, %1; cvt.u32.u64 %0, t; }"
        : "=r"(a) : "l"(p));
    return a;
}

__device__ __forceinline__ void ldmx4(uint32_t* r, uint32_t addr) {
    asm volatile("ldmatrix.sync.aligned.m8n8.x4.shared.b16 {%0,%1,%2,%3}, [%4];"
                 : "=r"(r[0]), "=r"(r[1]), "=r"(r[2]), "=r"(r[3]) : "r"(addr));
}

__device__ __forceinline__ void ldmx4t(uint32_t* r, uint32_t addr) {
    asm volatile("ldmatrix.sync.aligned.m8n8.x4.trans.shared.b16 {%0,%1,%2,%3}, [%4];"
                 : "=r"(r[0]), "=r"(r[1]), "=r"(r[2]), "=r"(r[3]) : "r"(addr));
}

__device__ __forceinline__ void mma_bf16(float* c, const uint32_t* a,
                                         const uint32_t* b) {
    asm volatile(
        "mma.sync.aligned.m16n8k16.row.col.f32.bf16.bf16.f32 "
        "{%0,%1,%2,%3}, {%4,%5,%6,%7}, {%8,%9}, {%0,%1,%2,%3};"
        : "+f"(c[0]), "+f"(c[1]), "+f"(c[2]), "+f"(c[3])
        : "r"(a[0]), "r"(a[1]), "r"(a[2]), "r"(a[3]), "r"(b[0]), "r"(b[1]));
}

__device__ __forceinline__ void split_pack(float x0, float x1,
                                           uint32_t& hi, uint32_t& lo) {
    __nv_bfloat16 h0 = __float2bfloat16(x0);
    __nv_bfloat16 h1 = __float2bfloat16(x1);
    __nv_bfloat16 l0 = __float2bfloat16(x0 - __bfloat162float(h0));
    __nv_bfloat16 l1 = __float2bfloat16(x1 - __bfloat162float(h1));
    hi = (uint32_t)__bfloat16_as_ushort(h0) | ((uint32_t)__bfloat16_as_ushort(h1) << 16);
    lo = (uint32_t)__bfloat16_as_ushort(l0) | ((uint32_t)__bfloat16_as_ushort(l1) << 16);
}

__device__ __forceinline__ void cpasync16(uint32_t saddr, const void* g) {
    asm volatile("cp.async.cg.shared.global [%0], [%1], 16;"
                 :: "r"(saddr), "l"(g));
}
#define CP_COMMIT() asm volatile("cp.async.commit_group;" ::: "memory")
#define CP_WAIT1()  asm volatile("cp.async.wait_group 1;" ::: "memory")
#define CP_WAIT0()  asm volatile("cp.async.wait_group 0;" ::: "memory")

// ===========================================================================
// Mask dtype detection (uint8 vs int32 storage of jnp.bool_)
// ===========================================================================
__global__ void detect_mask_kernel(const unsigned int* __restrict__ m)
{
    __shared__ int flag;
    if (threadIdx.x == 0) flag = 0;
    __syncthreads();
    int local = 0;
    for (int i = threadIdx.x; i < 16384; i += blockDim.x)
        if (m[i] > 1u) local = 1;
    if (local) atomicOr(&flag, 1);
    __syncthreads();
    if (threadIdx.x == 0) g_mask_u8 = flag;
}

// ===========================================================================
// fp32 -> split bf16 hi/lo planes (memory-bound, n4 = elems/4)
// ===========================================================================
__global__ void split_fp32(const float* __restrict__ X,
                           __nv_bfloat16* __restrict__ Hi,
                           __nv_bfloat16* __restrict__ Lo, int n4)
{
    int i = blockIdx.x * blockDim.x + threadIdx.x;
    if (i < n4) {
        float4 v = ((const float4*)X)[i];
        uint32_t h01, l01, h23, l23;
        split_pack(v.x, v.y, h01, l01);
        split_pack(v.z, v.w, h23, l23);
        ((uint2*)Hi)[i] = make_uint2(h01, h23);
        ((uint2*)Lo)[i] = make_uint2(l01, l23);
    }
}

// ===========================================================================
// Split-bf16 mma.sync GEMM on PRE-SPLIT operands, cp.async double-buffered.
// C[M,N] = A[M,K] @ W[N,K]^T. Tile 128x128x32; 8 warps (2x4), warp 64x32.
// Epilogue: optional fp32 C and/or scaled bf16 hi/lo planes.
// ===========================================================================
#define PK     40                      // padded row (32 data + 8) bf16
#define PLANEB (128 * PK * 2)          // 10240 B per plane per stage
#define STAGEB (4 * PLANEB)            // 40960 B
#define GSMEM  (2 * STAGEB)            // 81920 B

__device__ __forceinline__ void stage_load(
    uint32_t sbase, const __nv_bfloat16* __restrict__ Ahi,
    const __nv_bfloat16* __restrict__ Alo,
    const __nv_bfloat16* __restrict__ Whi,
    const __nv_bfloat16* __restrict__ Wlo,
    int tid, int bm, int bn, int K, int k0)
{
    #pragma unroll
    for (int it = 0; it < 2; it++) {
        int ch  = tid + it * 256;       // 512 chunks: 128 rows x 4 segs
        int r   = ch >> 2;
        int seg = ch & 3;
        uint32_t so = (uint32_t)(r * (PK * 2) + seg * 16);
        size_t goA = (size_t)(bm + r) * K + k0 + seg * 8;
        size_t goW = (size_t)(bn + r) * K + k0 + seg * 8;
        cpasync16(sbase + 0 * PLANEB + so, Ahi + goA);
        cpasync16(sbase + 1 * PLANEB + so, Alo + goA);
        cpasync16(sbase + 2 * PLANEB + so, Whi + goW);
        cpasync16(sbase + 3 * PLANEB + so, Wlo + goW);
    }
}

__global__ void __launch_bounds__(256, 2)
gemm_bf16(const __nv_bfloat16* __restrict__ Ahi,
          const __nv_bfloat16* __restrict__ Alo,
          const __nv_bfloat16* __restrict__ Whi,
          const __nv_bfloat16* __restrict__ Wlo,
          float* __restrict__ C,
          __nv_bfloat16* __restrict__ Phi,
          __nv_bfloat16* __restrict__ Plo,
          float oscale, int M, int N, int K)
{
    extern __shared__ char smem[];
    const uint32_t sb = smem_u32(smem);

    const int tid  = threadIdx.x;
    const int lane = tid & 31;
    const int wid  = tid >> 5;
    const int wm   = wid >> 2;
    const int wn   = wid & 3;
    const int bm   = blockIdx.y * 128;
    const int bn   = blockIdx.x * 128;

    float acc[16][4];
    #pragma unroll
    for (int i = 0; i < 16; i++)
        #pragma unroll
        for (int j = 0; j < 4; j++) acc[i][j] = 0.f;

    const uint32_t offA =
        (uint32_t)(((wm * 64 + (lane & 15)) * PK + ((lane >> 4) << 3)) * 2);
    const uint32_t offB =
        (uint32_t)(((wn * 32 + (((lane >> 3) >> 1) << 3) + (lane & 7)) * PK
                    + (((lane >> 3) & 1) << 3)) * 2);

    const int nch = K >> 5;
    stage_load(sb, Ahi, Alo, Whi, Wlo, tid, bm, bn, K, 0);
    CP_COMMIT();

    for (int ck = 0; ck < nch; ck++) {
        if (ck + 1 < nch) {
            stage_load(sb + ((ck + 1) & 1) * STAGEB, Ahi, Alo, Whi, Wlo,
                       tid, bm, bn, K, (ck + 1) << 5);
            CP_COMMIT();
            CP_WAIT1();
        } else {
            CP_WAIT0();
        }
        __syncthreads();

        const uint32_t st = sb + (ck & 1) * STAGEB;
        const uint32_t bAhi = st, bAlo = st + PLANEB;
        const uint32_t bWhi = st + 2 * PLANEB, bWlo = st + 3 * PLANEB;

        #pragma unroll
        for (int ks = 0; ks < 2; ks++) {
            const uint32_t kb = (uint32_t)(ks * 32);
            uint32_t bh[8], bl[8];
            #pragma unroll
            for (int ntp = 0; ntp < 2; ntp++) {
                uint32_t ro = (uint32_t)(ntp * 16 * PK * 2);
                ldmx4(&bh[ntp * 4], bWhi + offB + ro + kb);
                ldmx4(&bl[ntp * 4], bWlo + offB + ro + kb);
            }
            #pragma unroll
            for (int mt = 0; mt < 4; mt++) {
                uint32_t ah[4], al[4];
                uint32_t ro = (uint32_t)(mt * 16 * PK * 2);
                ldmx4(ah, bAhi + offA + ro + kb);
                ldmx4(al, bAlo + offA + ro + kb);
                #pragma unroll
                for (int nt = 0; nt < 4; nt++) {
                    float* c = acc[mt * 4 + nt];
                    mma_bf16(c, ah, &bh[nt * 2]);
                    mma_bf16(c, ah, &bl[nt * 2]);
                    mma_bf16(c, al, &bh[nt * 2]);
                }
            }
        }
        __syncthreads();
    }

    const int g = lane >> 2;
    const int t = lane & 3;
    #pragma unroll
    for (int mt = 0; mt < 4; mt++) {
        #pragma unroll
        for (int nt = 0; nt < 4; nt++) {
            const float* c = acc[mt * 4 + nt];
            int row = bm + wm * 64 + mt * 16 + g;
            int col = bn + wn * 32 + nt * 8 + 2 * t;
            if (C) {
                *(float2*)(C + (size_t)row * N + col)       = make_float2(c[0], c[1]);
                *(float2*)(C + (size_t)(row + 8) * N + col) = make_float2(c[2], c[3]);
            }
            if (Phi) {
                uint32_t hh, ll;
                split_pack(c[0] * oscale, c[1] * oscale, hh, ll);
                *(uint32_t*)(Phi + (size_t)row * N + col) = hh;
                *(uint32_t*)(Plo + (size_t)row * N + col) = ll;
                split_pack(c[2] * oscale, c[3] * oscale, hh, ll);
                *(uint32_t*)(Phi + (size_t)(row + 8) * N + col) = hh;
                *(uint32_t*)(Plo + (size_t)(row + 8) * N + col) = ll;
            }
        }
    }
}

// ===========================================================================
// Flash attention, split-bf16 mma.sync, PRE-SPLIT Q/K/V planes (scale folded
// into Q planes at projection epilogue). BQ=128, BKV=64, 8 warps.
// ===========================================================================
#define PKQ 136   // padded row (128 dh bf16 + 8)
#define PMK 72    // mask tile padded row (64 + 8)

struct FlashSmem2 {
    __nv_bfloat16 Qhi[128 * PKQ];
    __nv_bfloat16 Qlo[128 * PKQ];
    __nv_bfloat16 Khi[64 * PKQ];
    __nv_bfloat16 Klo[64 * PKQ];
    __nv_bfloat16 Vhi[64 * PKQ];
    __nv_bfloat16 Vlo[64 * PKQ];
    unsigned char Msk[128 * PMK];
};   // 148480 bytes

__global__ void __launch_bounds__(256, 1)
flash_mma(const __nv_bfloat16* __restrict__ Qhi, const __nv_bfloat16* __restrict__ Qlo,
          const __nv_bfloat16* __restrict__ Khi, const __nv_bfloat16* __restrict__ Klo,
          const __nv_bfloat16* __restrict__ Vhi, const __nv_bfloat16* __restrict__ Vlo,
          const void* __restrict__ mask_raw, float* __restrict__ ctx)
{
    extern __shared__ char smraw[];
    FlashSmem2* sm = reinterpret_cast<FlashSmem2*>(smraw);

    const int tid  = threadIdx.x;
    const int lane = tid & 31;
    const int w    = tid >> 5;
    const int q0   = blockIdx.x * 128;
    const int bh   = blockIdx.y;
    const int b    = bh >> 4;
    const int h    = bh & 15;
    const int mu8  = g_mask_u8;

    // ---- copy pre-split Q tile (128 x 128 bf16 x2 planes) ----
    const __nv_bfloat16* qh_ = Qhi + ((size_t)b * SEQ + q0) * DIM + h * DH;
    const __nv_bfloat16* ql_ = Qlo + ((size_t)b * SEQ + q0) * DIM + h * DH;
    #pragma unroll
    for (int it = 0; it < 8; it++) {
        int li = tid + it * 256;          // 2048 = 128 rows x 16 uint4
        int r  = li >> 4, c = li & 15;
        uint32_t so = (uint32_t)(r * (PKQ * 2) + c * 16);
        *(uint4*)((char*)sm->Qhi + so) = *(const uint4*)(qh_ + (size_t)r * DIM + c * 8);
        *(uint4*)((char*)sm->Qlo + so) = *(const uint4*)(ql_ + (size_t)r * DIM + c * 8);
    }

    const uint32_t bQhi = smem_u32(sm->Qhi), bQlo = smem_u32(sm->Qlo);
    const uint32_t bKhi = smem_u32(sm->Khi), bKlo = smem_u32(sm->Klo);
    const uint32_t bVhi = smem_u32(sm->Vhi), bVlo = smem_u32(sm->Vlo);

    const uint32_t offA =
        (uint32_t)(((w * 16 + (lane & 15)) * PKQ + ((lane >> 4) << 3)) * 2);
    const uint32_t offB =
        (uint32_t)(((((lane >> 4) & 1) * 8 + (lane & 7)) * PKQ
                    + (((lane >> 3) & 1) << 3)) * 2);
    const uint32_t offV =
        (uint32_t)((((lane & 7) + (((lane >> 3) & 1) << 3)) * PKQ
                    + (((lane >> 4) & 1) << 3)) * 2);

    float Oa[16][4];
    #pragma unroll
    for (int i = 0; i < 16; i++)
        #pragma unroll
        for (int j = 0; j < 4; j++) Oa[i][j] = 0.f;

    float m_g = -1e30f, m_g8 = -1e30f, l_g = 0.f, l_g8 = 0.f;
    const int g = lane >> 2, t = lane & 3;
    const int rg = w * 16 + g, rg8 = rg + 8;

    for (int k0 = 0; k0 < SEQ; k0 += 64) {
        __syncthreads();   // smem reuse guard (also covers initial Q stores)

        // ---- copy pre-split K/V tiles (64 x 128 x 4 planes) ----
        const __nv_bfloat16* kh_ = Khi + ((size_t)b * SEQ + k0) * DIM + h * DH;
        const __nv_bfloat16* kl_ = Klo + ((size_t)b * SEQ + k0) * DIM + h * DH;
        const __nv_bfloat16* vh_ = Vhi + ((size_t)b * SEQ + k0) * DIM + h * DH;
        const __nv_bfloat16* vl_ = Vlo + ((size_t)b * SEQ + k0) * DIM + h * DH;
        #pragma unroll
        for (int it = 0; it < 4; it++) {
            int li = tid + it * 256;      // 1024 = 64 rows x 16 uint4
            int r  = li >> 4, c = li & 15;
            uint32_t so = (uint32_t)(r * (PKQ * 2) + c * 16);
            size_t go = (size_t)r * DIM + c * 8;
            *(uint4*)((char*)sm->Khi + so) = *(const uint4*)(kh_ + go);
            *(uint4*)((char*)sm->Klo + so) = *(const uint4*)(kl_ + go);
            *(uint4*)((char*)sm->Vhi + so) = *(const uint4*)(vh_ + go);
            *(uint4*)((char*)sm->Vlo + so) = *(const uint4*)(vl_ + go);
        }

        // ---- stage mask tile (128 q x 64 k) as u8 ----
        if (mu8) {
            const unsigned char* mb = (const unsigned char*)mask_raw
                + (size_t)b * SEQ * SEQ + (size_t)q0 * SEQ + k0;
            #pragma unroll
            for (int it = 0; it < 8; it++) {
                int li = tid + it * 256;
                int r  = li >> 4, c4 = li & 15;
                *(uint32_t*)(sm->Msk + r * PMK + c4 * 4) =
                    *(const uint32_t*)(mb + (size_t)r * SEQ + c4 * 4);
            }
        } else {
            const int* mb = (const int*)mask_raw
                + (size_t)b * SEQ * SEQ + (size_t)q0 * SEQ + k0;
            #pragma unroll
            for (int it = 0; it < 8; it++) {
                int li = tid + it * 256;
                int r  = li >> 4, c4 = li & 15;
                int4 mv = *(const int4*)(mb + (size_t)r * SEQ + c4 * 4);
                uint32_t pk = (mv.x ? 1u : 0u) | ((mv.y ? 1u : 0u) << 8)
                            | ((mv.z ? 1u : 0u) << 16) | ((mv.w ? 1u : 0u) << 24);
                *(uint32_t*)(sm->Msk + r * PMK + c4 * 4) = pk;
            }
        }
        __syncthreads();

        // ---- S = Q . K^T  (split bf16, 3 combos) ----
        float sacc[8][4];
        #pragma unroll
        for (int i = 0; i < 8; i++)
            #pragma unroll
            for (int j = 0; j < 4; j++) sacc[i][j] = 0.f;

        #pragma unroll
        for (int ks = 0; ks < 8; ks++) {
            const uint32_t kb = (uint32_t)(ks * 32);
            uint32_t qh2[4], ql2[4];
            ldmx4(qh2, bQhi + offA + kb);
            ldmx4(ql2, bQlo + offA + kb);
            #pragma unroll
            for (int ntp = 0; ntp < 4; ntp++) {
                const uint32_t ro = (uint32_t)(ntp * 16 * PKQ * 2);
                uint32_t bh2[4], bl2[4];
                ldmx4(bh2, bKhi + offB + ro + kb);
                ldmx4(bl2, bKlo + offB + ro + kb);
                #pragma unroll
                for (int hf = 0; hf < 2; hf++) {
                    float* c = sacc[2 * ntp + hf];
                    mma_bf16(c, qh2, &bh2[hf * 2]);
                    mma_bf16(c, qh2, &bl2[hf * 2]);
                    mma_bf16(c, ql2, &bh2[hf * 2]);
                }
            }
        }

        // ---- mask + online softmax (intra-quad reductions) ----
        float mg = -1e30f, mg8 = -1e30f;
        #pragma unroll
        for (int nt = 0; nt < 8; nt++) {
            float* c = sacc[nt];
            int colb = nt * 8 + 2 * t;
            uchar2 ma  = *(const uchar2*)(sm->Msk + rg  * PMK + colb);
            uchar2 mb2 = *(const uchar2*)(sm->Msk + rg8 * PMK + colb);
            c[0] += ma.x  ? NEGV : 0.f;
            c[1] += ma.y  ? NEGV : 0.f;
            c[2] += mb2.x ? NEGV : 0.f;
            c[3] += mb2.y ? NEGV : 0.f;
            mg  = fmaxf(mg,  fmaxf(c[0], c[1]));
            mg8 = fmaxf(mg8, fmaxf(c[2], c[3]));
        }
        mg  = fmaxf(mg,  __shfl_xor_sync(0xffffffffu, mg, 1));
        mg  = fmaxf(mg,  __shfl_xor_sync(0xffffffffu, mg, 2));
        mg8 = fmaxf(mg8, __shfl_xor_sync(0xffffffffu, mg8, 1));
        mg8 = fmaxf(mg8, __shfl_xor_sync(0xffffffffu, mg8, 2));

        float mn  = fmaxf(m_g,  mg);
        float mn8 = fmaxf(m_g8, mg8);
        float ag  = __expf(m_g  - mn);
        float ag8 = __expf(m_g8 - mn8);
        m_g = mn; m_g8 = mn8;

        float sg = 0.f, sg8 = 0.f;
        #pragma unroll
        for (int nt = 0; nt < 8; nt++) {
            float* c = sacc[nt];
            c[0] = __expf(c[0] - mn);
            c[1] = __expf(c[1] - mn);
            c[2] = __expf(c[2] - mn8);
            c[3] = __expf(c[3] - mn8);
            sg  += c[0] + c[1];
            sg8 += c[2] + c[3];
        }
        sg  += __shfl_xor_sync(0xffffffffu, sg, 1);
        sg  += __shfl_xor_sync(0xffffffffu, sg, 2);
        sg8 += __shfl_xor_sync(0xffffffffu, sg8, 1);
        sg8 += __shfl_xor_sync(0xffffffffu, sg8, 2);
        l_g  = l_g  * ag  + sg;
        l_g8 = l_g8 * ag8 + sg8;

        #pragma unroll
        for (int nt = 0; nt < 16; nt++) {
            Oa[nt][0] *= ag;  Oa[nt][1] *= ag;
            Oa[nt][2] *= ag8; Oa[nt][3] *= ag8;
        }

        // ---- O += P . V  (P split in-register, V split in smem) ----
        #pragma unroll
        for (int ks = 0; ks < 4; ks++) {
            uint32_t ph_[4], pl_[4];
            split_pack(sacc[2*ks][0],   sacc[2*ks][1],   ph_[0], pl_[0]);
            split_pack(sacc[2*ks][2],   sacc[2*ks][3],   ph_[1], pl_[1]);
            split_pack(sacc[2*ks+1][0], sacc[2*ks+1][1], ph_[2], pl_[2]);
            split_pack(sacc[2*ks+1][2], sacc[2*ks+1][3], ph_[3], pl_[3]);
            const uint32_t kro = (uint32_t)(ks * 16 * PKQ * 2);
            #pragma unroll
            for (int ntp = 0; ntp < 8; ntp++) {
                const uint32_t no = (uint32_t)(ntp * 16 * 2);
                uint32_t vh2[4], vl2[4];
                ldmx4t(vh2, bVhi + offV + kro + no);
                ldmx4t(vl2, bVlo + offV + kro + no);
                #pragma unroll
                for (int hf = 0; hf < 2; hf++) {
                    float* o = Oa[2 * ntp + hf];
                    mma_bf16(o, ph_, &vh2[hf * 2]);
                    mma_bf16(o, ph_, &vl2[hf * 2]);
                    mma_bf16(o, pl_, &vh2[hf * 2]);
                }
            }
        }
    }

    // ---- finalize: O / l, write ctx[b, q, h*DH + col] ----
    const float ig  = 1.f / l_g;
    const float ig8 = 1.f / l_g8;
    float* ob = ctx + ((size_t)b * SEQ + q0) * DIM + h * DH;
    #pragma unroll
    for (int nt = 0; nt < 16; nt++) {
        int col = nt * 8 + 2 * t;
        *(float2*)(ob + (size_t)rg  * DIM + col) =
            make_float2(Oa[nt][0] * ig,  Oa[nt][1] * ig);
        *(float2*)(ob + (size_t)rg8 * DIM + col) =
            make_float2(Oa[nt][2] * ig8, Oa[nt][3] * ig8);
    }
}

// ===========================================================================
// Launch
// ===========================================================================
extern "C" void kernel_launch(void* const* d_in, const int* in_sizes, int n_in,
                              void* d_out, int out_size)
{
    const float* q    = (const float*)d_in[0];
    const float* k    = (const float*)d_in[1];
    const float* v    = (const float*)d_in[2];
    const void*  mask = d_in[3];
    const float* Wq   = (const float*)d_in[4];
    const float* Wk   = (const float*)d_in[5];
    const float* Wv   = (const float*)d_in[6];
    const float* Wo   = (const float*)d_in[7];

    float* out = (float*)d_out;
    const size_t plane = (size_t)MROWS * DIM;
    float* kp = out + plane;
    float* vp = out + 2 * plane;

    __nv_bfloat16 *Ahi, *Alo, *Whi, *Wlo, *Qhi, *Qlo, *Khi, *Klo, *Vhi, *Vlo;
    float* ctx;
    cudaGetSymbolAddress((void**)&Ahi, g_Ahi);
    cudaGetSymbolAddress((void**)&Alo, g_Alo);
    cudaGetSymbolAddress((void**)&Whi, g_Whi);
    cudaGetSymbolAddress((void**)&Wlo, g_Wlo);
    cudaGetSymbolAddress((void**)&Qhi, g_Qhi);
    cudaGetSymbolAddress((void**)&Qlo, g_Qlo);
    cudaGetSymbolAddress((void**)&Khi, g_Khi);
    cudaGetSymbolAddress((void**)&Klo, g_Klo);
    cudaGetSymbolAddress((void**)&Vhi, g_Vhi);
    cudaGetSymbolAddress((void**)&Vlo, g_Vlo);
    cudaGetSymbolAddress((void**)&ctx, g_ctx);

    const int nA4 = (int)(plane / 4);                 // 2M
    const int nW4 = (int)((size_t)DIM * DIM / 4);     // 1M
    const float qscale = 0.08838834764831843f;        // 1/sqrt(128)

    dim3 gg(DIM / 128, MROWS / 128);                  // (16, 32)

    detect_mask_kernel<<<1, 256>>>((const unsigned int*)mask);

    cudaFuncSetAttribute(gemm_bf16, cudaFuncAttributeMaxDynamicSharedMemorySize,
                         GSMEM);
    cudaFuncSetAttribute(flash_mma, cudaFuncAttributeMaxDynamicSharedMemorySize,
                         (int)sizeof(FlashSmem2));

    // Q projection -> scaled split planes only
    split_fp32<<<nA4 / 256, 256>>>(q,  Ahi, Alo, nA4);
    split_fp32<<<nW4 / 256, 256>>>(Wq, Whi, Wlo, nW4);
    gemm_bf16<<<gg, 256, GSMEM>>>(Ahi, Alo, Whi, Wlo, nullptr, Qhi, Qlo,
                                  qscale, MROWS, DIM, DIM);

    // K projection -> fp32 output + split planes
    split_fp32<<<nA4 / 256, 256>>>(k,  Ahi, Alo, nA4);
    split_fp32<<<nW4 / 256, 256>>>(Wk, Whi, Wlo, nW4);
    gemm_bf16<<<gg, 256, GSMEM>>>(Ahi, Alo, Whi, Wlo, kp, Khi, Klo,
                                  1.0f, MROWS, DIM, DIM);

    // V projection -> fp32 output + split planes
    split_fp32<<<nA4 / 256, 256>>>(v,  Ahi, Alo, nA4);
    split_fp32<<<nW4 / 256, 256>>>(Wv, Whi, Wlo, nW4);
    gemm_bf16<<<gg, 256, GSMEM>>>(Ahi, Alo, Whi, Wlo, vp, Vhi, Vlo,
                                  1.0f, MROWS, DIM, DIM);

    // Attention on pre-split planes
    flash_mma<<<dim3(SEQ / 128, BATCH * HEADS), 256, sizeof(FlashSmem2)>>>(
        Qhi, Qlo, Khi, Klo, Vhi, Vlo, mask, ctx);

    // Output projection (fp32 only)
    split_fp32<<<nA4 / 256, 256>>>(ctx, Ahi, Alo, nA4);
    split_fp32<<<nW4 / 256, 256>>>(Wo, Whi, Wlo, nW4);
    gemm_bf16<<<gg, 256, GSMEM>>>(Ahi, Alo, Whi, Wlo, out, nullptr, nullptr,
                                  1.0f, MROWS, DIM, DIM);
}